// round 6
// baseline (speedup 1.0000x reference)
#include <cuda_runtime.h>
#include <cstdint>
#include <math.h>

#define EMBED   1024
#define HIDDEN  2048
#define BATCH   8192
#define DTOT    3072          // EMBED + HIDDEN
#define NGATES  8192          // 4 * HIDDEN

#define BM   128
#define BN   128
#define BK   32
#define ASTR 36               // padded smem stride: bank = (36*g + t) % 32 = 4g+t, conflict-free
#define TBUF (128 * ASTR)     // 4608 words per tile buffer

// Scratch (allocation-free rule: __device__ globals)
__device__ float g_gates[(size_t)BATCH * NGATES];   // 268 MB: pre-activation gates
__device__ float g_o[(size_t)BATCH * HIDDEN];       // 67 MB: sigmoid(o-gate)

// ---------------------------------------------------------------------------
// tf32 helpers
// ---------------------------------------------------------------------------
__device__ __forceinline__ unsigned f2tf(float f) {
    unsigned u;
    asm("cvt.rna.tf32.f32 %0, %1;" : "=r"(u) : "f"(f));   // round-to-nearest: unbiased
    return u;
}

__device__ __forceinline__ void mma8(float c[4],
                                     unsigned a0, unsigned a1, unsigned a2, unsigned a3,
                                     unsigned b0, unsigned b1) {
    asm volatile(
        "mma.sync.aligned.m16n8k8.row.col.f32.tf32.tf32.f32 "
        "{%0,%1,%2,%3}, {%4,%5,%6,%7}, {%8,%9}, {%0,%1,%2,%3};"
        : "+f"(c[0]), "+f"(c[1]), "+f"(c[2]), "+f"(c[3])
        : "r"(a0), "r"(a1), "r"(a2), "r"(a3), "r"(b0), "r"(b1));
}

// One 128x128x32 tile worth of MMAs (4 k-steps of 8)
__device__ __forceinline__ void compute_tile(const unsigned* __restrict__ As,
                                             const unsigned* __restrict__ Bs,
                                             int warp_m, int warp_n, int g, int t,
                                             float acc[4][4][4]) {
    #pragma unroll
    for (int ks = 0; ks < 4; ks++) {
        const int kk = ks * 8 + t;
        unsigned a[4][4], b[4][2];
        #pragma unroll
        for (int mi = 0; mi < 4; mi++) {
            const int r = warp_m * 64 + mi * 16 + g;
            a[mi][0] = As[r * ASTR + kk];
            a[mi][1] = As[(r + 8) * ASTR + kk];
            a[mi][2] = As[r * ASTR + kk + 4];
            a[mi][3] = As[(r + 8) * ASTR + kk + 4];
        }
        #pragma unroll
        for (int nj = 0; nj < 4; nj++) {
            const int c = warp_n * 32 + nj * 8 + g;
            b[nj][0] = Bs[c * ASTR + kk];
            b[nj][1] = Bs[c * ASTR + kk + 4];
        }
        #pragma unroll
        for (int mi = 0; mi < 4; mi++)
            #pragma unroll
            for (int nj = 0; nj < 4; nj++)
                mma8(acc[mi][nj], a[mi][0], a[mi][1], a[mi][2], a[mi][3],
                     b[nj][0], b[nj][1]);
    }
}

// cvt.rna + store one staged 128x32 tile (4 float4 per thread) into smem
__device__ __forceinline__ void stage_store(unsigned* __restrict__ dst,
                                            const float4* __restrict__ r, int tid) {
    #pragma unroll
    for (int j = 0; j < 4; j++) {
        const int idx = tid + j * 256;
        const int row = idx >> 3, c4 = idx & 7;
        uint4 u;
        u.x = f2tf(r[j].x); u.y = f2tf(r[j].y);
        u.z = f2tf(r[j].z); u.w = f2tf(r[j].w);
        *reinterpret_cast<uint4*>(&dst[row * ASTR + c4 * 4]) = u;   // 144B row pitch: 16B aligned
    }
}

// ---------------------------------------------------------------------------
// Kernel 1: gates = concat(x, short) @ concat(Wf,Wi,Wc,Wo)^T   (no bias here)
// ---------------------------------------------------------------------------
__global__ __launch_bounds__(256, 1)
void gates_gemm(const float* __restrict__ x, const float* __restrict__ st,
                const float* __restrict__ Wf, const float* __restrict__ Wi,
                const float* __restrict__ Wc, const float* __restrict__ Wo) {
    extern __shared__ unsigned smem[];
    unsigned* As = smem;             // 2 * TBUF
    unsigned* Bs = smem + 2 * TBUF;  // 2 * TBUF

    const int tid = threadIdx.x;
    const int lane = tid & 31, warp = tid >> 5;
    const int g = lane >> 2, t = lane & 3;
    const int warp_m = warp >> 2, warp_n = warp & 3;   // 2 x 4 warps -> 64x32 warp tiles
    const int bm = blockIdx.y, bn = blockIdx.x;

    const int ngate = bn * BN;
    const int gate = ngate >> 11;                       // which of the 4 weight mats
    const float* Wsel = (gate == 0) ? Wf : (gate == 1) ? Wi : (gate == 2) ? Wc : Wo;
    const float* Bbase = Wsel + (size_t)(ngate & 2047) * DTOT;

    float acc[4][4][4];
    #pragma unroll
    for (int mi = 0; mi < 4; mi++)
        #pragma unroll
        for (int nj = 0; nj < 4; nj++)
            #pragma unroll
            for (int q = 0; q < 4; q++) acc[mi][nj][q] = 0.f;

    float4 ra[4], rb[4];
    auto loadAB = [&](int kt) {
        const int k0 = kt * BK;
        const float* Asrc; int lda;
        if (k0 < EMBED) { Asrc = x + (size_t)bm * BM * EMBED + k0;             lda = EMBED;  }
        else            { Asrc = st + (size_t)bm * BM * HIDDEN + (k0 - EMBED); lda = HIDDEN; }
        const float* Bsrc = Bbase + k0;
        #pragma unroll
        for (int j = 0; j < 4; j++) {
            const int idx = tid + j * 256;
            const int row = idx >> 3, c4 = idx & 7;
            ra[j] = *reinterpret_cast<const float4*>(Asrc + (size_t)row * lda + c4 * 4);
            rb[j] = *reinterpret_cast<const float4*>(Bsrc + (size_t)row * DTOT + c4 * 4);
        }
    };

    loadAB(0);
    stage_store(As, ra, tid);
    stage_store(Bs, rb, tid);
    __syncthreads();

    const int KT = DTOT / BK;   // 96
    for (int kt = 0; kt < KT; kt++) {
        const int cur = kt & 1, nxt = cur ^ 1;
        if (kt + 1 < KT) loadAB(kt + 1);
        compute_tile(As + cur * TBUF, Bs + cur * TBUF, warp_m, warp_n, g, t, acc);
        if (kt + 1 < KT) {
            stage_store(As + nxt * TBUF, ra, tid);
            stage_store(Bs + nxt * TBUF, rb, tid);
        }
        __syncthreads();
    }

    float* out = g_gates + (size_t)(bm * BM) * NGATES + ngate;
    #pragma unroll
    for (int mi = 0; mi < 4; mi++) {
        const int r0 = warp_m * 64 + mi * 16 + g;
        #pragma unroll
        for (int nj = 0; nj < 4; nj++) {
            const int c0 = warp_n * 32 + nj * 8 + t * 2;
            *reinterpret_cast<float2*>(&out[(size_t)r0 * NGATES + c0]) =
                make_float2(acc[mi][nj][0], acc[mi][nj][1]);
            *reinterpret_cast<float2*>(&out[(size_t)(r0 + 8) * NGATES + c0]) =
                make_float2(acc[mi][nj][2], acc[mi][nj][3]);
        }
    }
}

// ---------------------------------------------------------------------------
// Kernel 2: elementwise gate math. Writes C_new into d_out[B*H:], o into g_o.
// ---------------------------------------------------------------------------
__global__ void lstm_ew(const float* __restrict__ lt,
                        const float* __restrict__ bf, const float* __restrict__ bi,
                        const float* __restrict__ bc, const float* __restrict__ bo,
                        float* __restrict__ cnew) {
    const size_t i = ((size_t)blockIdx.x * blockDim.x + threadIdx.x) * 4;
    const int row = (int)(i >> 11);
    const int col = (int)(i & 2047);
    const float* grow = g_gates + (size_t)row * NGATES + col;

    const float4 gf = *reinterpret_cast<const float4*>(grow);
    const float4 gi = *reinterpret_cast<const float4*>(grow + HIDDEN);
    const float4 gc = *reinterpret_cast<const float4*>(grow + 2 * HIDDEN);
    const float4 go = *reinterpret_cast<const float4*>(grow + 3 * HIDDEN);
    const float4 vbf = *reinterpret_cast<const float4*>(bf + col);
    const float4 vbi = *reinterpret_cast<const float4*>(bi + col);
    const float4 vbc = *reinterpret_cast<const float4*>(bc + col);
    const float4 vbo = *reinterpret_cast<const float4*>(bo + col);
    const float4 vlt = *reinterpret_cast<const float4*>(lt + i);

    float4 cn, oo;
#define SIG(v) (1.f / (1.f + expf(-(v))))
    cn.x = SIG(gf.x + vbf.x) * vlt.x + SIG(gi.x + vbi.x) * tanhf(gc.x + vbc.x);
    cn.y = SIG(gf.y + vbf.y) * vlt.y + SIG(gi.y + vbi.y) * tanhf(gc.y + vbc.y);
    cn.z = SIG(gf.z + vbf.z) * vlt.z + SIG(gi.z + vbi.z) * tanhf(gc.z + vbc.z);
    cn.w = SIG(gf.w + vbf.w) * vlt.w + SIG(gi.w + vbi.w) * tanhf(gc.w + vbc.w);
    oo.x = SIG(go.x + vbo.x);
    oo.y = SIG(go.y + vbo.y);
    oo.z = SIG(go.z + vbo.z);
    oo.w = SIG(go.w + vbo.w);
#undef SIG
    *reinterpret_cast<float4*>(cnew + i) = cn;
    *reinterpret_cast<float4*>(g_o + i)  = oo;
}

// ---------------------------------------------------------------------------
// Kernel 3: output = tanh(C_new @ W_h2o^T + b_h2o) * o
// ---------------------------------------------------------------------------
__global__ __launch_bounds__(256, 1)
void out_gemm(const float* __restrict__ cnew, const float* __restrict__ W,
              const float* __restrict__ bias, float* __restrict__ out) {
    extern __shared__ unsigned smem[];
    unsigned* As = smem;
    unsigned* Bs = smem + 2 * TBUF;

    const int tid = threadIdx.x;
    const int lane = tid & 31, warp = tid >> 5;
    const int g = lane >> 2, t = lane & 3;
    const int warp_m = warp >> 2, warp_n = warp & 3;
    const int bm = blockIdx.y, bn = blockIdx.x;

    const float* Abase = cnew + (size_t)bm * BM * HIDDEN;
    const float* Bbase = W + (size_t)bn * BN * HIDDEN;

    float acc[4][4][4];
    #pragma unroll
    for (int mi = 0; mi < 4; mi++)
        #pragma unroll
        for (int nj = 0; nj < 4; nj++)
            #pragma unroll
            for (int q = 0; q < 4; q++) acc[mi][nj][q] = 0.f;

    float4 ra[4], rb[4];
    auto loadAB = [&](int kt) {
        const int k0 = kt * BK;
        #pragma unroll
        for (int j = 0; j < 4; j++) {
            const int idx = tid + j * 256;
            const int row = idx >> 3, c4 = idx & 7;
            ra[j] = *reinterpret_cast<const float4*>(Abase + (size_t)row * HIDDEN + k0 + c4 * 4);
            rb[j] = *reinterpret_cast<const float4*>(Bbase + (size_t)row * HIDDEN + k0 + c4 * 4);
        }
    };

    loadAB(0);
    stage_store(As, ra, tid);
    stage_store(Bs, rb, tid);
    __syncthreads();

    const int KT = HIDDEN / BK;   // 64
    for (int kt = 0; kt < KT; kt++) {
        const int cur = kt & 1, nxt = cur ^ 1;
        if (kt + 1 < KT) loadAB(kt + 1);
        compute_tile(As + cur * TBUF, Bs + cur * TBUF, warp_m, warp_n, g, t, acc);
        if (kt + 1 < KT) {
            stage_store(As + nxt * TBUF, ra, tid);
            stage_store(Bs + nxt * TBUF, rb, tid);
        }
        __syncthreads();
    }

    // Fused epilogue: tanh(acc + bias) * o
    #pragma unroll
    for (int mi = 0; mi < 4; mi++) {
        const int r0 = bm * BM + warp_m * 64 + mi * 16 + g;
        #pragma unroll
        for (int nj = 0; nj < 4; nj++) {
            const int c0 = bn * BN + warp_n * 32 + nj * 8 + t * 2;
            const float b0 = bias[c0], b1 = bias[c0 + 1];
            {
                const size_t off = (size_t)r0 * HIDDEN + c0;
                out[off]     = tanhf(acc[mi][nj][0] + b0) * g_o[off];
                out[off + 1] = tanhf(acc[mi][nj][1] + b1) * g_o[off + 1];
            }
            {
                const size_t off = (size_t)(r0 + 8) * HIDDEN + c0;
                out[off]     = tanhf(acc[mi][nj][2] + b0) * g_o[off];
                out[off + 1] = tanhf(acc[mi][nj][3] + b1) * g_o[off + 1];
            }
        }
    }
}

// ---------------------------------------------------------------------------
// Launch
// ---------------------------------------------------------------------------
extern "C" void kernel_launch(void* const* d_in, const int* in_sizes, int n_in,
                              void* d_out, int out_size) {
    const float* x    = (const float*)d_in[0];
    const float* st   = (const float*)d_in[1];
    const float* lt   = (const float*)d_in[2];
    const float* Wf   = (const float*)d_in[3];
    const float* bf   = (const float*)d_in[4];
    const float* Wi   = (const float*)d_in[5];
    const float* bi   = (const float*)d_in[6];
    const float* Wc   = (const float*)d_in[7];
    const float* bc   = (const float*)d_in[8];
    const float* Wo   = (const float*)d_in[9];
    const float* bo   = (const float*)d_in[10];
    const float* Wh2o = (const float*)d_in[11];
    const float* bh2o = (const float*)d_in[12];

    float* out  = (float*)d_out;                       // [B, H] output
    float* cnew = out + (size_t)BATCH * HIDDEN;        // [B, H] C_new (second half of d_out)

    const int smem_bytes = 4 * TBUF * (int)sizeof(unsigned);   // 73728
    cudaFuncSetAttribute(gates_gemm, cudaFuncAttributeMaxDynamicSharedMemorySize, smem_bytes);
    cudaFuncSetAttribute(out_gemm,   cudaFuncAttributeMaxDynamicSharedMemorySize, smem_bytes);

    dim3 grid1(NGATES / BN, BATCH / BM);   // 64 x 64
    gates_gemm<<<grid1, 256, smem_bytes>>>(x, st, Wf, Wi, Wc, Wo);

    const int n4 = BATCH * HIDDEN / 4;     // 4,194,304
    lstm_ew<<<n4 / 256, 256>>>(lt, bf, bi, bc, bo, cnew);

    dim3 grid2(HIDDEN / BN, BATCH / BM);   // 16 x 64
    out_gemm<<<grid2, 256, smem_bytes>>>(cnew, Wh2o, bh2o, out);
}

// round 11
// speedup vs baseline: 1.0727x; 1.0727x over previous
#include <cuda_runtime.h>
#include <cstdint>
#include <math.h>

#define EMBED   1024
#define HIDDEN  2048
#define BATCH   8192
#define DTOT    3072          // EMBED + HIDDEN
#define NGATES  8192          // 4 * HIDDEN

#define BM     128
#define BN     128
#define BK     32
#define ASTR   36             // padded smem stride (words): conflict-free fragment LDS
#define TBUF   (128 * ASTR)   // 4608 words per tile buffer
#define STAGES 4

// ---------------------------------------------------------------------------
// Scratch (allocation-free rule: __device__ globals).  547 MB total.
// g_cw is a UNION: during GEMM1 it holds tf32-rounded concat(x, short) [B, DTOT];
// after lstm_ew its first B*H floats hold tf32-rounded C_new for GEMM2.
// round_pack rewrites the whole region at the start of every replay, so the
// aliasing is deterministic across graph replays.
// ---------------------------------------------------------------------------
__device__ float g_gates[(size_t)BATCH * NGATES];   // 268 MB: pre-activation gates
__device__ float g_o[(size_t)BATCH * HIDDEN];       //  67 MB: sigmoid(o-gate)
__device__ float g_cw[(size_t)BATCH * DTOT];        //  96 MB: comb (GEMM1) / C_new rounded (GEMM2)
__device__ float g_W[(size_t)NGATES * DTOT];        // 100 MB: tf32-rounded concat(Wf,Wi,Wc,Wo)
__device__ float g_Wh[(size_t)HIDDEN * HIDDEN];     //  16 MB: tf32-rounded W_h2o

// ---------------------------------------------------------------------------
// tf32 + cp.async helpers
// ---------------------------------------------------------------------------
__device__ __forceinline__ unsigned f2tf(float f) {
    unsigned u;
    asm("cvt.rna.tf32.f32 %0, %1;" : "=r"(u) : "f"(f));   // round-to-nearest: unbiased
    return u;
}
__device__ __forceinline__ float4 round4(float4 v) {
    float4 r;
    r.x = __uint_as_float(f2tf(v.x));
    r.y = __uint_as_float(f2tf(v.y));
    r.z = __uint_as_float(f2tf(v.z));
    r.w = __uint_as_float(f2tf(v.w));
    return r;
}

__device__ __forceinline__ void cp16(void* smem_dst, const void* gsrc) {
    unsigned s = (unsigned)__cvta_generic_to_shared(smem_dst);
    asm volatile("cp.async.cg.shared.global [%0], [%1], 16;\n" :: "r"(s), "l"(gsrc));
}
__device__ __forceinline__ void cp_commit() {
    asm volatile("cp.async.commit_group;\n");
}
template<int N> __device__ __forceinline__ void cp_wait() {
    asm volatile("cp.async.wait_group %0;\n" :: "n"(N));
}

__device__ __forceinline__ void mma8(float c[4],
                                     unsigned a0, unsigned a1, unsigned a2, unsigned a3,
                                     unsigned b0, unsigned b1) {
    asm volatile(
        "mma.sync.aligned.m16n8k8.row.col.f32.tf32.tf32.f32 "
        "{%0,%1,%2,%3}, {%4,%5,%6,%7}, {%8,%9}, {%0,%1,%2,%3};"
        : "+f"(c[0]), "+f"(c[1]), "+f"(c[2]), "+f"(c[3])
        : "r"(a0), "r"(a1), "r"(a2), "r"(a3), "r"(b0), "r"(b1));
}

// One 128x128x32 tile worth of MMAs (4 k-steps of 8). Operands are already
// tf32-valid fp32 bit patterns (pre-rounded), so no cvt in the mainloop.
__device__ __forceinline__ void compute_tile(const unsigned* __restrict__ As,
                                             const unsigned* __restrict__ Bs,
                                             int warp_m, int warp_n, int g, int t,
                                             float acc[4][4][4]) {
    #pragma unroll
    for (int ks = 0; ks < 4; ks++) {
        const int kk = ks * 8 + t;
        unsigned a[4][4], b[4][2];
        #pragma unroll
        for (int mi = 0; mi < 4; mi++) {
            const int r = warp_m * 64 + mi * 16 + g;
            a[mi][0] = As[r * ASTR + kk];
            a[mi][1] = As[(r + 8) * ASTR + kk];
            a[mi][2] = As[r * ASTR + kk + 4];
            a[mi][3] = As[(r + 8) * ASTR + kk + 4];
        }
        #pragma unroll
        for (int nj = 0; nj < 4; nj++) {
            const int c = warp_n * 32 + nj * 8 + g;
            b[nj][0] = Bs[c * ASTR + kk];
            b[nj][1] = Bs[c * ASTR + kk + 4];
        }
        #pragma unroll
        for (int mi = 0; mi < 4; mi++)
            #pragma unroll
            for (int nj = 0; nj < 4; nj++)
                mma8(acc[mi][nj], a[mi][0], a[mi][1], a[mi][2], a[mi][3],
                     b[nj][0], b[nj][1]);
    }
}

// Issue cp.async for one 128x32 A tile + one 128x32 B tile into a stage buffer
__device__ __forceinline__ void stage_load(unsigned* __restrict__ sA,
                                           unsigned* __restrict__ sB,
                                           const float* __restrict__ Ag,
                                           const float* __restrict__ Bg,
                                           int ldA, int ldB, int k0, int tid) {
    #pragma unroll
    for (int j = 0; j < 4; j++) {
        const int idx = tid + j * 256;
        const int row = idx >> 3, c4 = idx & 7;
        cp16(&sA[row * ASTR + c4 * 4], Ag + (size_t)row * ldA + k0 + c4 * 4);
        cp16(&sB[row * ASTR + c4 * 4], Bg + (size_t)row * ldB + k0 + c4 * 4);
    }
}

// ---------------------------------------------------------------------------
// Pre-round kernels (fp32 -> tf32-valid fp32), run once per call.
// Destinations are the __device__ scratch symbols directly (no
// cudaGetSymbolAddress anywhere in kernel_launch).
// ---------------------------------------------------------------------------
__global__ void round_W(const float4* __restrict__ s, int mat, int n4) {
    const int i = blockIdx.x * blockDim.x + threadIdx.x;
    if (i < n4)
        reinterpret_cast<float4*>(g_W)[(size_t)mat * n4 + i] = round4(s[i]);
}

__global__ void round_Wh(const float4* __restrict__ s, int n4) {
    const int i = blockIdx.x * blockDim.x + threadIdx.x;
    if (i < n4)
        reinterpret_cast<float4*>(g_Wh)[i] = round4(s[i]);
}

// Pack src [rows][scol4*4] into g_cw (row stride DTOT) at column offset doff4*4
__global__ void round_pack(const float4* __restrict__ s, int scol4, int doff4, int n4) {
    const int i = blockIdx.x * blockDim.x + threadIdx.x;
    if (i < n4) {
        const int row = i / scol4, c = i % scol4;
        reinterpret_cast<float4*>(g_cw)[(size_t)row * (DTOT / 4) + doff4 + c] = round4(s[i]);
    }
}

// ---------------------------------------------------------------------------
// Kernel 1: gates = comb @ W_all^T   (no bias here)
// ---------------------------------------------------------------------------
__global__ __launch_bounds__(256, 1)
void gates_gemm() {
    extern __shared__ unsigned smem[];
    const int tid = threadIdx.x;
    const int lane = tid & 31, warp = tid >> 5;
    const int g = lane >> 2, t = lane & 3;
    const int warp_m = warp >> 2, warp_n = warp & 3;   // 2 x 4 warps -> 64x32 warp tiles
    const int bm = blockIdx.y, bn = blockIdx.x;

    const float* Ag = g_cw + (size_t)bm * BM * DTOT;
    const float* Bg = g_W + (size_t)bn * BN * DTOT;

    float acc[4][4][4];
    #pragma unroll
    for (int mi = 0; mi < 4; mi++)
        #pragma unroll
        for (int nj = 0; nj < 4; nj++)
            #pragma unroll
            for (int q = 0; q < 4; q++) acc[mi][nj][q] = 0.f;

    const int KT = DTOT / BK;   // 96

    // Prologue: fill STAGES-1 stages
    #pragma unroll
    for (int s = 0; s < STAGES - 1; s++) {
        unsigned* p = smem + s * 2 * TBUF;
        stage_load(p, p + TBUF, Ag, Bg, DTOT, DTOT, s * BK, tid);
        cp_commit();
    }

    for (int kt = 0; kt < KT; kt++) {
        cp_wait<STAGES - 2>();       // group kt complete (this thread)
        __syncthreads();             // all threads' data visible; compute(kt-1) done
        const int nk = kt + STAGES - 1;
        if (nk < KT) {
            unsigned* p = smem + (nk & (STAGES - 1)) * 2 * TBUF;
            stage_load(p, p + TBUF, Ag, Bg, DTOT, DTOT, nk * BK, tid);
        }
        cp_commit();                 // commit even when empty: keeps group count in sync
        unsigned* cur = smem + (kt & (STAGES - 1)) * 2 * TBUF;
        compute_tile(cur, cur + TBUF, warp_m, warp_n, g, t, acc);
    }

    float* out = g_gates + (size_t)(bm * BM) * NGATES + (size_t)bn * BN;
    #pragma unroll
    for (int mi = 0; mi < 4; mi++) {
        const int r0 = warp_m * 64 + mi * 16 + g;
        #pragma unroll
        for (int nj = 0; nj < 4; nj++) {
            const int c0 = warp_n * 32 + nj * 8 + t * 2;
            *reinterpret_cast<float2*>(&out[(size_t)r0 * NGATES + c0]) =
                make_float2(acc[mi][nj][0], acc[mi][nj][1]);
            *reinterpret_cast<float2*>(&out[(size_t)(r0 + 8) * NGATES + c0]) =
                make_float2(acc[mi][nj][2], acc[mi][nj][3]);
        }
    }
}

// ---------------------------------------------------------------------------
// Kernel 2: elementwise gate math.
// Writes exact C_new into d_out[B*H:], rounded C_new into g_cw[0:B*H], o into g_o.
// ---------------------------------------------------------------------------
__global__ void lstm_ew(const float* __restrict__ lt,
                        const float* __restrict__ bf, const float* __restrict__ bi,
                        const float* __restrict__ bc, const float* __restrict__ bo,
                        float* __restrict__ cnew) {
    const size_t i = ((size_t)blockIdx.x * blockDim.x + threadIdx.x) * 4;
    const int row = (int)(i >> 11);
    const int col = (int)(i & 2047);
    const float* grow = g_gates + (size_t)row * NGATES + col;

    const float4 gf = *reinterpret_cast<const float4*>(grow);
    const float4 gi = *reinterpret_cast<const float4*>(grow + HIDDEN);
    const float4 gc = *reinterpret_cast<const float4*>(grow + 2 * HIDDEN);
    const float4 go = *reinterpret_cast<const float4*>(grow + 3 * HIDDEN);
    const float4 vbf = *reinterpret_cast<const float4*>(bf + col);
    const float4 vbi = *reinterpret_cast<const float4*>(bi + col);
    const float4 vbc = *reinterpret_cast<const float4*>(bc + col);
    const float4 vbo = *reinterpret_cast<const float4*>(bo + col);
    const float4 vlt = *reinterpret_cast<const float4*>(lt + i);

    float4 cn, oo;
#define SIG(v) (1.f / (1.f + expf(-(v))))
    cn.x = SIG(gf.x + vbf.x) * vlt.x + SIG(gi.x + vbi.x) * tanhf(gc.x + vbc.x);
    cn.y = SIG(gf.y + vbf.y) * vlt.y + SIG(gi.y + vbi.y) * tanhf(gc.y + vbc.y);
    cn.z = SIG(gf.z + vbf.z) * vlt.z + SIG(gi.z + vbi.z) * tanhf(gc.z + vbc.z);
    cn.w = SIG(gf.w + vbf.w) * vlt.w + SIG(gi.w + vbi.w) * tanhf(gc.w + vbc.w);
    oo.x = SIG(go.x + vbo.x);
    oo.y = SIG(go.y + vbo.y);
    oo.z = SIG(go.z + vbo.z);
    oo.w = SIG(go.w + vbo.w);
#undef SIG
    *reinterpret_cast<float4*>(cnew + i) = cn;                       // exact C_new -> output
    reinterpret_cast<float4*>(g_cw)[i / 4] = round4(cn);             // tf32-rounded -> GEMM2 input
    *reinterpret_cast<float4*>(g_o + i)  = oo;
}

// ---------------------------------------------------------------------------
// Kernel 3: output = tanh(C_new @ W_h2o^T + b_h2o) * o
// ---------------------------------------------------------------------------
__global__ __launch_bounds__(256, 1)
void out_gemm(const float* __restrict__ bias, float* __restrict__ out) {
    extern __shared__ unsigned smem[];
    const int tid = threadIdx.x;
    const int lane = tid & 31, warp = tid >> 5;
    const int g = lane >> 2, t = lane & 3;
    const int warp_m = warp >> 2, warp_n = warp & 3;
    const int bm = blockIdx.y, bn = blockIdx.x;

    const float* Ag = g_cw + (size_t)bm * BM * HIDDEN;   // rounded C_new region
    const float* Bg = g_Wh + (size_t)bn * BN * HIDDEN;

    float acc[4][4][4];
    #pragma unroll
    for (int mi = 0; mi < 4; mi++)
        #pragma unroll
        for (int nj = 0; nj < 4; nj++)
            #pragma unroll
            for (int q = 0; q < 4; q++) acc[mi][nj][q] = 0.f;

    const int KT = HIDDEN / BK;   // 64

    #pragma unroll
    for (int s = 0; s < STAGES - 1; s++) {
        unsigned* p = smem + s * 2 * TBUF;
        stage_load(p, p + TBUF, Ag, Bg, HIDDEN, HIDDEN, s * BK, tid);
        cp_commit();
    }

    for (int kt = 0; kt < KT; kt++) {
        cp_wait<STAGES - 2>();
        __syncthreads();
        const int nk = kt + STAGES - 1;
        if (nk < KT) {
            unsigned* p = smem + (nk & (STAGES - 1)) * 2 * TBUF;
            stage_load(p, p + TBUF, Ag, Bg, HIDDEN, HIDDEN, nk * BK, tid);
        }
        cp_commit();
        unsigned* cur = smem + (kt & (STAGES - 1)) * 2 * TBUF;
        compute_tile(cur, cur + TBUF, warp_m, warp_n, g, t, acc);
    }

    // Fused epilogue: tanh(acc + bias) * o
    #pragma unroll
    for (int mi = 0; mi < 4; mi++) {
        const int r0 = bm * BM + warp_m * 64 + mi * 16 + g;
        #pragma unroll
        for (int nj = 0; nj < 4; nj++) {
            const int c0 = bn * BN + warp_n * 32 + nj * 8 + t * 2;
            const float b0 = bias[c0], b1 = bias[c0 + 1];
            {
                const size_t off = (size_t)r0 * HIDDEN + c0;
                out[off]     = tanhf(acc[mi][nj][0] + b0) * g_o[off];
                out[off + 1] = tanhf(acc[mi][nj][1] + b1) * g_o[off + 1];
            }
            {
                const size_t off = (size_t)(r0 + 8) * HIDDEN + c0;
                out[off]     = tanhf(acc[mi][nj][2] + b0) * g_o[off];
                out[off + 1] = tanhf(acc[mi][nj][3] + b1) * g_o[off + 1];
            }
        }
    }
}

// ---------------------------------------------------------------------------
// Launch
// ---------------------------------------------------------------------------
extern "C" void kernel_launch(void* const* d_in, const int* in_sizes, int n_in,
                              void* d_out, int out_size) {
    const float* x    = (const float*)d_in[0];
    const float* st   = (const float*)d_in[1];
    const float* lt   = (const float*)d_in[2];
    const float* Wf   = (const float*)d_in[3];
    const float* bf   = (const float*)d_in[4];
    const float* Wi   = (const float*)d_in[5];
    const float* bi   = (const float*)d_in[6];
    const float* Wc   = (const float*)d_in[7];
    const float* bc   = (const float*)d_in[8];
    const float* Wo   = (const float*)d_in[9];
    const float* bo   = (const float*)d_in[10];
    const float* Wh2o = (const float*)d_in[11];
    const float* bh2o = (const float*)d_in[12];

    float* out  = (float*)d_out;                       // [B, H] output
    float* cnew = out + (size_t)BATCH * HIDDEN;        // [B, H] C_new (second half of d_out)

    // ---- Pre-round to tf32 (weights + activations) ----
    const int wn4 = HIDDEN * DTOT / 4;                 // 1,572,864 per gate matrix
    round_W<<<wn4 / 256, 256>>>((const float4*)Wf, 0, wn4);
    round_W<<<wn4 / 256, 256>>>((const float4*)Wi, 1, wn4);
    round_W<<<wn4 / 256, 256>>>((const float4*)Wc, 2, wn4);
    round_W<<<wn4 / 256, 256>>>((const float4*)Wo, 3, wn4);
    const int hn4 = HIDDEN * HIDDEN / 4;               // 1,048,576
    round_Wh<<<hn4 / 256, 256>>>((const float4*)Wh2o, hn4);

    const int xn4 = BATCH * EMBED / 4;                 // 2,097,152
    round_pack<<<xn4 / 256, 256>>>((const float4*)x, EMBED / 4, 0, xn4);
    const int sn4 = BATCH * HIDDEN / 4;                // 4,194,304
    round_pack<<<sn4 / 256, 256>>>((const float4*)st, HIDDEN / 4, EMBED / 4, sn4);

    // ---- GEMM1 + elementwise + GEMM2 ----
    const int smem_bytes = STAGES * 2 * TBUF * (int)sizeof(unsigned);   // 147456
    cudaFuncSetAttribute(gates_gemm, cudaFuncAttributeMaxDynamicSharedMemorySize, smem_bytes);
    cudaFuncSetAttribute(out_gemm,   cudaFuncAttributeMaxDynamicSharedMemorySize, smem_bytes);

    dim3 grid1(NGATES / BN, BATCH / BM);   // 64 x 64
    gates_gemm<<<grid1, 256, smem_bytes>>>();

    lstm_ew<<<sn4 / 256, 256>>>(lt, bf, bi, bc, bo, cnew);

    dim3 grid2(HIDDEN / BN, BATCH / BM);   // 16 x 64
    out_gemm<<<grid2, 256, smem_bytes>>>(bh2o, out);
}

// round 16
// speedup vs baseline: 1.2681x; 1.1822x over previous
#include <cuda_runtime.h>
#include <cstdint>
#include <math.h>

#define EMBED   1024
#define HIDDEN  2048
#define BATCH   8192
#define DTOT    3072          // EMBED + HIDDEN
#define NGATES  8192          // 4 * HIDDEN

#define BM     128
#define BN     128
#define BK     32
#define WM     64             // warp tile M (4 warps: 2x2)
#define WN     64             // warp tile N
#define ASTR   36             // padded smem stride (words): conflict-free fragment LDS
#define TBUF   (128 * ASTR)   // 4608 words per tile buffer (18432 B)
#define STAGES 3
#define SMEM_BYTES (STAGES * 2 * TBUF * 4)   // 110592 B -> 2 CTAs/SM

// ---------------------------------------------------------------------------
// Scratch (allocation-free rule: __device__ globals).  547 MB (R11 footprint).
// g_cw union: tf32-rounded concat(x, short) during GEMM1; first B*H floats
// hold tf32-rounded C_new for GEMM2 (rewritten every replay -> deterministic).
// ---------------------------------------------------------------------------
__device__ float g_gates[(size_t)BATCH * NGATES];   // 268 MB pre-activation gates
__device__ float g_o[(size_t)BATCH * HIDDEN];       //  67 MB sigmoid(o-gate)
__device__ float g_cw[(size_t)BATCH * DTOT];        //  96 MB comb / C_new rounded
__device__ float g_W[(size_t)NGATES * DTOT];        // 100 MB tf32-rounded [Wf;Wi;Wc;Wo]
__device__ float g_Wh[(size_t)HIDDEN * HIDDEN];     //  16 MB tf32-rounded W_h2o

// ---------------------------------------------------------------------------
// tf32 + cp.async helpers
// ---------------------------------------------------------------------------
__device__ __forceinline__ unsigned f2tf(float f) {
    unsigned u;
    asm("cvt.rna.tf32.f32 %0, %1;" : "=r"(u) : "f"(f));   // round-to-nearest: unbiased
    return u;
}
__device__ __forceinline__ float4 round4(float4 v) {
    float4 r;
    r.x = __uint_as_float(f2tf(v.x));
    r.y = __uint_as_float(f2tf(v.y));
    r.z = __uint_as_float(f2tf(v.z));
    r.w = __uint_as_float(f2tf(v.w));
    return r;
}
__device__ __forceinline__ void cp16(void* smem_dst, const void* gsrc) {
    unsigned s = (unsigned)__cvta_generic_to_shared(smem_dst);
    asm volatile("cp.async.cg.shared.global [%0], [%1], 16;\n" :: "r"(s), "l"(gsrc));
}
__device__ __forceinline__ void cp_commit() {
    asm volatile("cp.async.commit_group;\n");
}
template<int N> __device__ __forceinline__ void cp_wait() {
    asm volatile("cp.async.wait_group %0;\n" :: "n"(N));
}
__device__ __forceinline__ void mma8(float c[4],
                                     unsigned a0, unsigned a1, unsigned a2, unsigned a3,
                                     unsigned b0, unsigned b1) {
    asm volatile(
        "mma.sync.aligned.m16n8k8.row.col.f32.tf32.tf32.f32 "
        "{%0,%1,%2,%3}, {%4,%5,%6,%7}, {%8,%9}, {%0,%1,%2,%3};"
        : "+f"(c[0]), "+f"(c[1]), "+f"(c[2]), "+f"(c[3])
        : "r"(a0), "r"(a1), "r"(a2), "r"(a3), "r"(b0), "r"(b1));
}

// One 128x128x32 CTA tile: this warp's 64x64 share. Operands pre-rounded ->
// no cvt in mainloop. LDS:MMA ratio 1.0 (128 LDS : 128 MMA per warp K-tile).
__device__ __forceinline__ void compute_tile(const unsigned* __restrict__ As,
                                             const unsigned* __restrict__ Bs,
                                             int wm, int wn, int g, int t,
                                             float acc[4][8][4]) {
    #pragma unroll
    for (int ks = 0; ks < 4; ks++) {
        const int kk = ks * 8 + t;
        unsigned a[4][4], b[8][2];
        #pragma unroll
        for (int mi = 0; mi < 4; mi++) {
            const int r = wm * WM + mi * 16 + g;
            a[mi][0] = As[r * ASTR + kk];
            a[mi][1] = As[(r + 8) * ASTR + kk];
            a[mi][2] = As[r * ASTR + kk + 4];
            a[mi][3] = As[(r + 8) * ASTR + kk + 4];
        }
        #pragma unroll
        for (int nj = 0; nj < 8; nj++) {
            const int c = wn * WN + nj * 8 + g;
            b[nj][0] = Bs[c * ASTR + kk];
            b[nj][1] = Bs[c * ASTR + kk + 4];
        }
        #pragma unroll
        for (int mi = 0; mi < 4; mi++)
            #pragma unroll
            for (int nj = 0; nj < 8; nj++)
                mma8(acc[mi][nj], a[mi][0], a[mi][1], a[mi][2], a[mi][3],
                     b[nj][0], b[nj][1]);
    }
}

// Issue cp.async for one 128x32 A tile + one 128x32 B tile (128 threads).
__device__ __forceinline__ void stage_load(unsigned* __restrict__ sA,
                                           unsigned* __restrict__ sB,
                                           const float* __restrict__ Ag,
                                           const float* __restrict__ Bg,
                                           int ldA, int ldB, int k0, int tid) {
    #pragma unroll
    for (int j = 0; j < 8; j++) {
        const int idx = tid + j * 128;
        const int row = idx >> 3, c4 = idx & 7;
        cp16(&sA[row * ASTR + c4 * 4], Ag + (size_t)row * ldA + k0 + c4 * 4);
        cp16(&sB[row * ASTR + c4 * 4], Bg + (size_t)row * ldB + k0 + c4 * 4);
    }
}

// ---------------------------------------------------------------------------
// Pre-round kernels (fp32 -> tf32-valid fp32), once per call.
// ---------------------------------------------------------------------------
__global__ void round_W(const float4* __restrict__ s, int mat, int n4) {
    const int i = blockIdx.x * blockDim.x + threadIdx.x;
    if (i < n4)
        reinterpret_cast<float4*>(g_W)[(size_t)mat * n4 + i] = round4(s[i]);
}
__global__ void round_Wh(const float4* __restrict__ s, int n4) {
    const int i = blockIdx.x * blockDim.x + threadIdx.x;
    if (i < n4)
        reinterpret_cast<float4*>(g_Wh)[i] = round4(s[i]);
}
__global__ void round_pack(const float4* __restrict__ s, int scol4, int doff4, int n4) {
    const int i = blockIdx.x * blockDim.x + threadIdx.x;
    if (i < n4) {
        const int row = i / scol4, c = i % scol4;
        reinterpret_cast<float4*>(g_cw)[(size_t)row * (DTOT / 4) + doff4 + c] = round4(s[i]);
    }
}

// ---------------------------------------------------------------------------
// Kernel 1: gates = comb @ W_all^T   (no bias here)
// ---------------------------------------------------------------------------
__global__ __launch_bounds__(128, 2)
void gates_gemm() {
    extern __shared__ unsigned smem[];
    const int tid = threadIdx.x;
    const int lane = tid & 31, warp = tid >> 5;
    const int g = lane >> 2, t = lane & 3;
    const int wm = warp >> 1, wn = warp & 1;           // 2 x 2 warps, 64x64 tiles
    const int bm = blockIdx.y, bn = blockIdx.x;

    const float* Ag = g_cw + (size_t)bm * BM * DTOT;
    const float* Bg = g_W + (size_t)bn * BN * DTOT;

    float acc[4][8][4];
    #pragma unroll
    for (int mi = 0; mi < 4; mi++)
        #pragma unroll
        for (int nj = 0; nj < 8; nj++)
            #pragma unroll
            for (int q = 0; q < 4; q++) acc[mi][nj][q] = 0.f;

    const int KT = DTOT / BK;   // 96

    #pragma unroll
    for (int s = 0; s < STAGES - 1; s++) {
        unsigned* p = smem + s * 2 * TBUF;
        stage_load(p, p + TBUF, Ag, Bg, DTOT, DTOT, s * BK, tid);
        cp_commit();
    }

    int cur = 0, nxt = STAGES - 1;
    for (int kt = 0; kt < KT; kt++) {
        cp_wait<STAGES - 2>();       // stage kt landed (this thread's groups)
        __syncthreads();             // all threads' data visible; compute(kt-1) done
        const int nk = kt + STAGES - 1;
        if (nk < KT) {
            unsigned* p = smem + nxt * 2 * TBUF;
            stage_load(p, p + TBUF, Ag, Bg, DTOT, DTOT, nk * BK, tid);
        }
        cp_commit();                 // commit every iter: keeps group count in sync
        unsigned* c = smem + cur * 2 * TBUF;
        compute_tile(c, c + TBUF, wm, wn, g, t, acc);
        if (++cur == STAGES) cur = 0;
        if (++nxt == STAGES) nxt = 0;
    }

    float* out = g_gates + (size_t)(bm * BM) * NGATES + (size_t)bn * BN;
    #pragma unroll
    for (int mi = 0; mi < 4; mi++) {
        const int r0 = wm * WM + mi * 16 + g;
        #pragma unroll
        for (int nj = 0; nj < 8; nj++) {
            const int c0 = wn * WN + nj * 8 + t * 2;
            *reinterpret_cast<float2*>(&out[(size_t)r0 * NGATES + c0]) =
                make_float2(acc[mi][nj][0], acc[mi][nj][1]);
            *reinterpret_cast<float2*>(&out[(size_t)(r0 + 8) * NGATES + c0]) =
                make_float2(acc[mi][nj][2], acc[mi][nj][3]);
        }
    }
}

// ---------------------------------------------------------------------------
// Kernel 2: elementwise gate math.
// Writes exact C_new into d_out[B*H:], rounded C_new into g_cw[0:B*H], o into g_o.
// ---------------------------------------------------------------------------
__global__ void lstm_ew(const float* __restrict__ lt,
                        const float* __restrict__ bf, const float* __restrict__ bi,
                        const float* __restrict__ bc, const float* __restrict__ bo,
                        float* __restrict__ cnew) {
    const size_t i = ((size_t)blockIdx.x * blockDim.x + threadIdx.x) * 4;
    const int row = (int)(i >> 11);
    const int col = (int)(i & 2047);
    const float* grow = g_gates + (size_t)row * NGATES + col;

    const float4 gf = *reinterpret_cast<const float4*>(grow);
    const float4 gi = *reinterpret_cast<const float4*>(grow + HIDDEN);
    const float4 gc = *reinterpret_cast<const float4*>(grow + 2 * HIDDEN);
    const float4 go = *reinterpret_cast<const float4*>(grow + 3 * HIDDEN);
    const float4 vbf = *reinterpret_cast<const float4*>(bf + col);
    const float4 vbi = *reinterpret_cast<const float4*>(bi + col);
    const float4 vbc = *reinterpret_cast<const float4*>(bc + col);
    const float4 vbo = *reinterpret_cast<const float4*>(bo + col);
    const float4 vlt = *reinterpret_cast<const float4*>(lt + i);

    float4 cn, oo;
#define SIG(v) (1.f / (1.f + expf(-(v))))
    cn.x = SIG(gf.x + vbf.x) * vlt.x + SIG(gi.x + vbi.x) * tanhf(gc.x + vbc.x);
    cn.y = SIG(gf.y + vbf.y) * vlt.y + SIG(gi.y + vbi.y) * tanhf(gc.y + vbc.y);
    cn.z = SIG(gf.z + vbf.z) * vlt.z + SIG(gi.z + vbi.z) * tanhf(gc.z + vbc.z);
    cn.w = SIG(gf.w + vbf.w) * vlt.w + SIG(gi.w + vbi.w) * tanhf(gc.w + vbc.w);
    oo.x = SIG(go.x + vbo.x);
    oo.y = SIG(go.y + vbo.y);
    oo.z = SIG(go.z + vbo.z);
    oo.w = SIG(go.w + vbo.w);
#undef SIG
    *reinterpret_cast<float4*>(cnew + i)  = cn;          // exact C_new -> output
    reinterpret_cast<float4*>(g_cw)[i / 4] = round4(cn); // tf32-rounded -> GEMM2 input
    *reinterpret_cast<float4*>(g_o + i)   = oo;
}

// ---------------------------------------------------------------------------
// Kernel 3: output = tanh(C_new @ W_h2o^T + b_h2o) * o
// ---------------------------------------------------------------------------
__global__ __launch_bounds__(128, 2)
void out_gemm(const float* __restrict__ bias, float* __restrict__ out) {
    extern __shared__ unsigned smem[];
    const int tid = threadIdx.x;
    const int lane = tid & 31, warp = tid >> 5;
    const int g = lane >> 2, t = lane & 3;
    const int wm = warp >> 1, wn = warp & 1;
    const int bm = blockIdx.y, bn = blockIdx.x;

    const float* Ag = g_cw + (size_t)bm * BM * HIDDEN;   // rounded C_new region
    const float* Bg = g_Wh + (size_t)bn * BN * HIDDEN;

    float acc[4][8][4];
    #pragma unroll
    for (int mi = 0; mi < 4; mi++)
        #pragma unroll
        for (int nj = 0; nj < 8; nj++)
            #pragma unroll
            for (int q = 0; q < 4; q++) acc[mi][nj][q] = 0.f;

    const int KT = HIDDEN / BK;   // 64

    #pragma unroll
    for (int s = 0; s < STAGES - 1; s++) {
        unsigned* p = smem + s * 2 * TBUF;
        stage_load(p, p + TBUF, Ag, Bg, HIDDEN, HIDDEN, s * BK, tid);
        cp_commit();
    }

    int cur = 0, nxt = STAGES - 1;
    for (int kt = 0; kt < KT; kt++) {
        cp_wait<STAGES - 2>();
        __syncthreads();
        const int nk = kt + STAGES - 1;
        if (nk < KT) {
            unsigned* p = smem + nxt * 2 * TBUF;
            stage_load(p, p + TBUF, Ag, Bg, HIDDEN, HIDDEN, nk * BK, tid);
        }
        cp_commit();
        unsigned* c = smem + cur * 2 * TBUF;
        compute_tile(c, c + TBUF, wm, wn, g, t, acc);
        if (++cur == STAGES) cur = 0;
        if (++nxt == STAGES) nxt = 0;
    }

    // Fused epilogue: tanh(acc + bias) * o
    #pragma unroll
    for (int mi = 0; mi < 4; mi++) {
        const int r0 = bm * BM + wm * WM + mi * 16 + g;
        #pragma unroll
        for (int nj = 0; nj < 8; nj++) {
            const int c0 = bn * BN + wn * WN + nj * 8 + t * 2;
            const float b0 = bias[c0], b1 = bias[c0 + 1];
            {
                const size_t off = (size_t)r0 * HIDDEN + c0;
                out[off]     = tanhf(acc[mi][nj][0] + b0) * g_o[off];
                out[off + 1] = tanhf(acc[mi][nj][1] + b1) * g_o[off + 1];
            }
            {
                const size_t off = (size_t)(r0 + 8) * HIDDEN + c0;
                out[off]     = tanhf(acc[mi][nj][2] + b0) * g_o[off];
                out[off + 1] = tanhf(acc[mi][nj][3] + b1) * g_o[off + 1];
            }
        }
    }
}

// ---------------------------------------------------------------------------
// Launch
// ---------------------------------------------------------------------------
extern "C" void kernel_launch(void* const* d_in, const int* in_sizes, int n_in,
                              void* d_out, int out_size) {
    const float* x    = (const float*)d_in[0];
    const float* st   = (const float*)d_in[1];
    const float* lt   = (const float*)d_in[2];
    const float* Wf   = (const float*)d_in[3];
    const float* bf   = (const float*)d_in[4];
    const float* Wi   = (const float*)d_in[5];
    const float* bi   = (const float*)d_in[6];
    const float* Wc   = (const float*)d_in[7];
    const float* bc   = (const float*)d_in[8];
    const float* Wo   = (const float*)d_in[9];
    const float* bo   = (const float*)d_in[10];
    const float* Wh2o = (const float*)d_in[11];
    const float* bh2o = (const float*)d_in[12];

    float* out  = (float*)d_out;                       // [B, H] output
    float* cnew = out + (size_t)BATCH * HIDDEN;        // [B, H] C_new (second half of d_out)

    // ---- Pre-round to tf32 (weights + activations) ----
    const int wn4 = HIDDEN * DTOT / 4;                 // 1,572,864 per gate matrix
    round_W<<<wn4 / 256, 256>>>((const float4*)Wf, 0, wn4);
    round_W<<<wn4 / 256, 256>>>((const float4*)Wi, 1, wn4);
    round_W<<<wn4 / 256, 256>>>((const float4*)Wc, 2, wn4);
    round_W<<<wn4 / 256, 256>>>((const float4*)Wo, 3, wn4);
    const int hn4 = HIDDEN * HIDDEN / 4;               // 1,048,576
    round_Wh<<<hn4 / 256, 256>>>((const float4*)Wh2o, hn4);

    const int xn4 = BATCH * EMBED / 4;
    round_pack<<<xn4 / 256, 256>>>((const float4*)x, EMBED / 4, 0, xn4);
    const int sn4 = BATCH * HIDDEN / 4;
    round_pack<<<sn4 / 256, 256>>>((const float4*)st, HIDDEN / 4, EMBED / 4, sn4);

    // ---- GEMM1 + elementwise + GEMM2 ----
    cudaFuncSetAttribute(gates_gemm, cudaFuncAttributeMaxDynamicSharedMemorySize, SMEM_BYTES);
    cudaFuncSetAttribute(out_gemm,   cudaFuncAttributeMaxDynamicSharedMemorySize, SMEM_BYTES);

    dim3 grid1(NGATES / BN, BATCH / BM);   // 64 x 64
    gates_gemm<<<grid1, 128, SMEM_BYTES>>>();

    lstm_ew<<<sn4 / 256, 256>>>(lt, bf, bi, bc, bo, cnew);

    dim3 grid2(HIDDEN / BN, BATCH / BM);   // 16 x 64
    out_gemm<<<grid2, 128, SMEM_BYTES>>>(bh2o, out);
}